// round 14
// baseline (speedup 1.0000x reference)
#include <cuda_runtime.h>

// AtmLayer v7: (row, column-quad) grid; one thread = one row x FOUR columns
// (two f32x2 pairs). Every weight LDS amortized over 4 columns (gas) /
// 8 streams (ext). Select-free gas elu, pre-scaled dup weights in smem.

#define TPB 128

typedef unsigned long long u64;
union F2U { u64 u; float2 f; };

__device__ __forceinline__ float2 fma2(float2 a, float2 b, float2 c) {
    F2U A, B, C, D; A.f = a; B.f = b; C.f = c;
    asm("fma.rn.f32x2 %0,%1,%2,%3;" : "=l"(D.u) : "l"(A.u), "l"(B.u), "l"(C.u));
    return D.f;
}
__device__ __forceinline__ float2 mul2(float2 a, float2 b) {
    F2U A, B, D; A.f = a; B.f = b;
    asm("mul.rn.f32x2 %0,%1,%2;" : "=l"(D.u) : "l"(A.u), "l"(B.u));
    return D.f;
}
__device__ __forceinline__ float2 add2(float2 a, float2 b) {
    F2U A, B, D; A.f = a; B.f = b;
    asm("add.rn.f32x2 %0,%1,%2;" : "=l"(D.u) : "l"(A.u), "l"(B.u));
    return D.f;
}
__device__ __forceinline__ float ex2_(float x) {
    float r; asm("ex2.approx.ftz.f32 %0,%1;" : "=f"(r) : "f"(x)); return r;
}

#define L2E 1.4426950408889634f
#define LN2 0.6931471805599453f

// comp idx: 0=h2o 1=h2o_sq 2=o3 3=co2 4=n2o 5=ch4 6=u
__constant__ int cNETS[29][7] = {
    {23, 0,52,65,74,77,86},
    {24, 1,53,66,75,78,87},
    {25, 2,54,67,76,79,88},
    {26, 3,80,-1,-1,-1,-1},
    {27, 4,81,-1,-1,-1,-1},
    {28, 5,68,-1,-1,-1,-1},
    {29, 6,69,-1,-1,-1,-1},
    {30, 3,82,-1,-1,-1,-1},
    {31, 4,83,-1,-1,-1,-1},
    {32, 9,70,-1,-1,-1,-1},
    {33,10,71,-1,-1,-1,-1},
    {34,11,84,-1,-1,-1,-1},
    {35,12,85,-1,-1,-1,-1},
    {36,13,72,-1,-1,-1,-1},
    {37,14,73,-1,-1,-1,-1},
    {38,15,89,-1,-1,-1,-1},
    {39,16,90,-1,-1,-1,-1},
    {40,17,55,91,-1,-1,-1},
    {41,18,56,92,-1,-1,-1},
    {42,19,57,93,-1,-1,-1},
    {43,20,58,94,-1,-1,-1},
    {44,21,59,95,-1,-1,-1},
    {45,22,60,96,-1,-1,-1},
    {46,-1,-1,-1,-1,-1,-1},
    {47,-1,-1,-1,-1,-1,-1},
    {48,61,-1,-1,-1,-1,-1},
    {49,62,-1,-1,-1,-1,-1},
    {50,63,97,-1,-1,-1,-1},
    {51,64,98,-1,-1,-1,-1},
};
__constant__ int cCIDX[29][7] = {
    {1,0,2,3,4,5,6},
    {1,0,2,3,4,5,6},
    {1,0,2,3,4,5,6},
    {1,0,5,0,0,0,0},
    {1,0,5,0,0,0,0},
    {1,0,3,0,0,0,0},
    {1,0,3,0,0,0,0},
    {1,0,5,0,0,0,0},
    {1,0,5,0,0,0,0},
    {1,0,3,0,0,0,0},
    {1,0,3,0,0,0,0},
    {1,0,5,0,0,0,0},
    {1,0,5,0,0,0,0},
    {1,0,3,0,0,0,0},
    {1,0,3,0,0,0,0},
    {1,0,6,0,0,0,0},
    {1,0,6,0,0,0,0},
    {1,0,2,6,0,0,0},
    {1,0,2,6,0,0,0},
    {1,0,2,6,0,0,0},
    {1,0,2,6,0,0,0},
    {1,0,2,6,0,0,0},
    {1,0,2,6,0,0,0},
    {1,0,0,0,0,0,0},
    {1,0,0,0,0,0,0},
    {1,2,0,0,0,0,0},
    {1,2,0,0,0,0,0},
    {1,2,6,0,0,0,0},
    {1,2,6,0,0,0,0},
};
__constant__ int cCNT[29] = {7,7,7,3,3,3,3,3,3,3,3,3,3,3,3,3,3,4,4,4,4,4,4,1,1,2,2,3,3};

struct __align__(16) GasNet {
    float2 w1[16];   // W1 * log2e, duplicated pairs; index [i*8 + u]
    float2 b1[8];    // b1 * log2e, dup
    float2 vln[8];   // W2 * ln2, dup
    float2 v[8];     // W2, dup
    float  bias;     // b2 - sum(W2)
    float  pad;
};
struct __align__(16) SmemT {
    GasNet g[7];
    float2 ew1[16][4];   // ext W1 dup, [j][i]
    float2 ev[16][4];    // ext W2 dup, [j][k], k=3 zero
    float2 eb1[16];      // ext b1 dup
    float  misc[5];      // lw, iw, eb0..2
    const float* comp[7];
};

template<int CNT>
__device__ __forceinline__ void row_body(
    SmemT* sm, int r,
    const float* __restrict__ temp, const float* __restrict__ pressure,
    const float* __restrict__ comp_h2o, const float* __restrict__ comp_h2o_sq,
    const float* __restrict__ comp_o3, const float* __restrict__ comp_co2,
    const float* __restrict__ comp_n2o, const float* __restrict__ comp_ch4,
    const float* __restrict__ comp_u,
    const float* __restrict__ lwp, const float* __restrict__ iwp,
    const float* __restrict__ mu, const float* __restrict__ mu_bar,
    const float* __restrict__ gas_W1, const float* __restrict__ gas_b1,
    const float* __restrict__ gas_W2, const float* __restrict__ gas_b2,
    const float* __restrict__ lw_w, const float* __restrict__ iw_w,
    const float* __restrict__ ext_W1, const float* __restrict__ ext_b1,
    const float* __restrict__ ext_W2, const float* __restrict__ ext_b2,
    float* __restrict__ out, int B)
{
    const int tid = threadIdx.x;

    // ---- staging: transform + duplicate weights ----
    #pragma unroll 2
    for (int i = tid; i < CNT * 33; i += TPB) {
        const int t = i / 33;
        const int k = i - t * 33;
        const int g = cNETS[r][t];
        GasNet& G = sm->g[t];
        if (k < 16) {
            const float w = gas_W1[g * 16 + k] * L2E;
            G.w1[k] = make_float2(w, w);
        } else if (k < 24) {
            const float w = gas_b1[g * 8 + (k - 16)] * L2E;
            G.b1[k - 16] = make_float2(w, w);
        } else if (k < 32) {
            const float w = gas_W2[g * 8 + (k - 24)];
            G.vln[k - 24] = make_float2(w * LN2, w * LN2);
            G.v[k - 24]   = make_float2(w, w);
        } else {
            float s = 0.0f;
            #pragma unroll
            for (int u = 0; u < 8; ++u) s += gas_W2[g * 8 + u];
            G.bias = gas_b2[g] - s;
        }
    }
    for (int i = tid; i < 64; i += TPB) {
        const int ii = i >> 4, j = i & 15;
        const float w = ext_W1[r * 64 + i];
        sm->ew1[j][ii] = make_float2(w, w);
    }
    for (int i = tid; i < 48; i += TPB) {
        const int j = i / 3, k = i - j * 3;
        const float w = ext_W2[r * 48 + i];
        sm->ev[j][k] = make_float2(w, w);
    }
    for (int i = tid; i < 16; i += TPB) {
        sm->ev[i][3] = make_float2(0.0f, 0.0f);
        const float w = ext_b1[r * 16 + i];
        sm->eb1[i] = make_float2(w, w);
    }
    if (tid < 5) {
        float v;
        if      (tid == 0) v = lw_w[r];
        else if (tid == 1) v = iw_w[r];
        else               v = ext_b2[r * 3 + (tid - 2)];
        sm->misc[tid] = v;
    }
    if (tid >= 8 && tid < 8 + CNT) {
        const int t = tid - 8;
        const float* ptrs[7] = {comp_h2o, comp_h2o_sq, comp_o3, comp_co2,
                                comp_n2o, comp_ch4, comp_u};
        sm->comp[t] = ptrs[cCIDX[r][t]];
    }
    __syncthreads();

    const int p4 = blockIdx.x * TPB + tid;     // quad index
    const int b0 = 4 * p4;
    if (b0 + 3 >= B) return;
    const int pp = 2 * p4;                     // float2-pair base index

    float2 X0[2], X1[2];
    X0[0] = reinterpret_cast<const float2*>(temp)[pp];
    X0[1] = reinterpret_cast<const float2*>(temp)[pp + 1];
    X1[0] = reinterpret_cast<const float2*>(pressure)[pp];
    X1[1] = reinterpret_cast<const float2*>(pressure)[pp + 1];

    // ---- gas nets: two packed pairs share every weight load ----
    float2 tau[2] = { make_float2(0.f, 0.f), make_float2(0.f, 0.f) };
    #pragma unroll
    for (int t = 0; t < CNT; ++t) {
        const GasNet& G = sm->g[t];
        float2 acc1[2] = { make_float2(0.f, 0.f), make_float2(0.f, 0.f) };
        float2 acc2[2] = { make_float2(0.f, 0.f), make_float2(0.f, 0.f) };
        #pragma unroll
        for (int u = 0; u < 8; ++u) {
            const float2 wa = G.w1[u];
            const float2 wb = G.w1[8 + u];
            const float2 bb = G.b1[u];
            const float2 vl = G.vln[u];
            const float2 vv = G.v[u];
            #pragma unroll
            for (int q = 0; q < 2; ++q) {
                const float2 zs = fma2(X1[q], wb, fma2(X0[q], wa, bb));
                const float2 mx = make_float2(fmaxf(zs.x, 0.f), fmaxf(zs.y, 0.f));
                const float2 ee = make_float2(ex2_(fminf(zs.x, 0.f)),
                                              ex2_(fminf(zs.y, 0.f)));
                acc1[q] = fma2(mx, vl, acc1[q]);
                acc2[q] = fma2(ee, vv, acc2[q]);
            }
        }
        const float2 cA = reinterpret_cast<const float2*>(sm->comp[t])[pp];
        const float2 cB = reinterpret_cast<const float2*>(sm->comp[t])[pp + 1];
        #pragma unroll
        for (int q = 0; q < 2; ++q) {
            const float2 acc = add2(acc1[q], acc2[q]);
            const float keA = fmaxf(acc.x + G.bias, 0.f);
            const float keB = fmaxf(acc.y + G.bias, 0.f);
            tau[q] = fma2(make_float2(keA, keB), q ? cB : cA, tau[q]);
        }
    }

    // ---- cloud terms + ext inputs ----
    float2 I1[2], I2[2], I3D[2], I3F[2], MUv[2], MUB[2];
    const float lwr = sm->misc[0], iwr = sm->misc[1];
    #pragma unroll
    for (int q = 0; q < 2; ++q) {
        const float2 LWP = reinterpret_cast<const float2*>(lwp)[pp + q];
        const float2 IWP = reinterpret_cast<const float2*>(iwp)[pp + q];
        MUv[q] = reinterpret_cast<const float2*>(mu)[pp + q];
        MUB[q] = reinterpret_cast<const float2*>(mu_bar)[pp + q];
        const float2 tlw = mul2(make_float2(lwr, lwr), LWP);
        const float2 tiw = mul2(make_float2(iwr, iwr), IWP);
        const float2 tt  = add2(tau[q], add2(tlw, tiw));
        const float2 rtt = make_float2(__fdividef(1.f, tt.x), __fdividef(1.f, tt.y));
        I1[q] = mul2(tlw, rtt);
        I2[q] = mul2(tiw, rtt);
        I3D[q] = make_float2(tt.x * __fdividef(1.f, MUv[q].x),
                             tt.y * __fdividef(1.f, MUv[q].y));
        I3F[q] = make_float2(tt.x * __fdividef(1.f, MUB[q].x),
                             tt.y * __fdividef(1.f, MUB[q].y));
    }

    // ---- ext net: 8 streams share every weight load ----
    const float eb0 = sm->misc[2], eb1v = sm->misc[3], eb2v = sm->misc[4];
    float2 ad0[2], ad1[2], ad2[2], af0[2], af1[2], af2[2];
    #pragma unroll
    for (int q = 0; q < 2; ++q) {
        ad0[q] = make_float2(eb0, eb0); ad1[q] = make_float2(eb1v, eb1v); ad2[q] = make_float2(eb2v, eb2v);
        af0[q] = ad0[q]; af1[q] = ad1[q]; af2[q] = ad2[q];
    }
    const float2 L2E2 = make_float2(L2E, L2E);
    #pragma unroll
    for (int j = 0; j < 16; ++j) {
        const float2 w0 = sm->ew1[j][0];
        const float2 w1v = sm->ew1[j][1];
        const float2 w2v = sm->ew1[j][2];
        const float2 w3v = sm->ew1[j][3];
        const float2 bj = sm->eb1[j];
        const float2 v0 = sm->ev[j][0];
        const float2 v1 = sm->ev[j][1];
        const float2 v2 = sm->ev[j][2];
        #pragma unroll
        for (int q = 0; q < 2; ++q) {
            const float2 base = fma2(I2[q], w1v, fma2(I1[q], w0, bj));
            const float2 zd = fma2(MUv[q], w3v, fma2(I3D[q], w2v, base));
            const float2 zf = fma2(MUB[q], w3v, fma2(I3F[q], w2v, base));
            const float2 td = mul2(zd, L2E2);
            const float2 tf = mul2(zf, L2E2);
            float2 hd, hf;
            hd.x = zd.x > 0.f ? zd.x : ex2_(td.x) - 1.f;
            hd.y = zd.y > 0.f ? zd.y : ex2_(td.y) - 1.f;
            hf.x = zf.x > 0.f ? zf.x : ex2_(tf.x) - 1.f;
            hf.y = zf.y > 0.f ? zf.y : ex2_(tf.y) - 1.f;
            ad0[q] = fma2(hd, v0, ad0[q]); ad1[q] = fma2(hd, v1, ad1[q]); ad2[q] = fma2(hd, v2, ad2[q]);
            af0[q] = fma2(hf, v0, af0[q]); af1[q] = fma2(hf, v1, af1[q]); af2[q] = fma2(hf, v2, af2[q]);
        }
    }

    const unsigned NB = (unsigned)B * 29u;
    const unsigned rb = (unsigned)r * (unsigned)B + (unsigned)b0;

    // softmax + stores: 12 contiguous floats per family -> 3 float4 stores
    float ed[12], ef[12];
    #pragma unroll
    for (int q = 0; q < 2; ++q) {
        // direct, lane x then lane y
        {
            const float a0 = fmaxf(ad0[q].x, 0.f), a1 = fmaxf(ad1[q].x, 0.f), a2 = fmaxf(ad2[q].x, 0.f);
            const float m = fmaxf(a0, fmaxf(a1, a2));
            const float e0 = ex2_((a0 - m) * L2E), e1 = ex2_((a1 - m) * L2E), e2 = ex2_((a2 - m) * L2E);
            const float inv = __fdividef(1.f, e0 + e1 + e2);
            ed[q * 6 + 0] = e0 * inv; ed[q * 6 + 1] = e1 * inv; ed[q * 6 + 2] = e2 * inv;
            const float b0v = fmaxf(ad0[q].y, 0.f), b1v = fmaxf(ad1[q].y, 0.f), b2v = fmaxf(ad2[q].y, 0.f);
            const float mB = fmaxf(b0v, fmaxf(b1v, b2v));
            const float f0 = ex2_((b0v - mB) * L2E), f1 = ex2_((b1v - mB) * L2E), f2 = ex2_((b2v - mB) * L2E);
            const float invB = __fdividef(1.f, f0 + f1 + f2);
            ed[q * 6 + 3] = f0 * invB; ed[q * 6 + 4] = f1 * invB; ed[q * 6 + 5] = f2 * invB;
        }
        // diffuse
        {
            const float a0 = fmaxf(af0[q].x, 0.f), a1 = fmaxf(af1[q].x, 0.f), a2 = fmaxf(af2[q].x, 0.f);
            const float m = fmaxf(a0, fmaxf(a1, a2));
            const float e0 = ex2_((a0 - m) * L2E), e1 = ex2_((a1 - m) * L2E), e2 = ex2_((a2 - m) * L2E);
            const float inv = __fdividef(1.f, e0 + e1 + e2);
            ef[q * 6 + 0] = e0 * inv; ef[q * 6 + 1] = e1 * inv; ef[q * 6 + 2] = e2 * inv;
            const float b0v = fmaxf(af0[q].y, 0.f), b1v = fmaxf(af1[q].y, 0.f), b2v = fmaxf(af2[q].y, 0.f);
            const float mB = fmaxf(b0v, fmaxf(b1v, b2v));
            const float f0 = ex2_((b0v - mB) * L2E), f1 = ex2_((b1v - mB) * L2E), f2 = ex2_((b2v - mB) * L2E);
            const float invB = __fdividef(1.f, f0 + f1 + f2);
            ef[q * 6 + 3] = f0 * invB; ef[q * 6 + 4] = f1 * invB; ef[q * 6 + 5] = f2 * invB;
        }
    }
    {
        float4* od = reinterpret_cast<float4*>(out + 2u * NB + rb * 3u);
        od[0] = make_float4(ed[0], ed[1], ed[2], ed[3]);
        od[1] = make_float4(ed[4], ed[5], ed[6], ed[7]);
        od[2] = make_float4(ed[8], ed[9], ed[10], ed[11]);
        float4* of = reinterpret_cast<float4*>(out + 5u * NB + rb * 3u);
        of[0] = make_float4(ef[0], ef[1], ef[2], ef[3]);
        of[1] = make_float4(ef[4], ef[5], ef[6], ef[7]);
        of[2] = make_float4(ef[8], ef[9], ef[10], ef[11]);
    }
    {
        float4 td, tf;
        td.x = ex2_(-I3D[0].x * L2E); td.y = ex2_(-I3D[0].y * L2E);
        td.z = ex2_(-I3D[1].x * L2E); td.w = ex2_(-I3D[1].y * L2E);
        tf.x = ex2_(-I3F[0].x * L2E); tf.y = ex2_(-I3F[0].y * L2E);
        tf.z = ex2_(-I3F[1].x * L2E); tf.w = ex2_(-I3F[1].y * L2E);
        reinterpret_cast<float4*>(out + rb)[0]      = td;
        reinterpret_cast<float4*>(out + NB + rb)[0] = tf;
    }
}

__global__ void __launch_bounds__(TPB)
atm_row_kernel(const float* __restrict__ temp,
               const float* __restrict__ pressure,
               const float* __restrict__ comp_h2o,
               const float* __restrict__ comp_h2o_sq,
               const float* __restrict__ comp_o3,
               const float* __restrict__ comp_co2,
               const float* __restrict__ comp_n2o,
               const float* __restrict__ comp_ch4,
               const float* __restrict__ comp_u,
               const float* __restrict__ lwp,
               const float* __restrict__ iwp,
               const float* __restrict__ mu,
               const float* __restrict__ mu_bar,
               const float* __restrict__ gas_W1,
               const float* __restrict__ gas_b1,
               const float* __restrict__ gas_W2,
               const float* __restrict__ gas_b2,
               const float* __restrict__ lw_w,
               const float* __restrict__ iw_w,
               const float* __restrict__ ext_W1,
               const float* __restrict__ ext_b1,
               const float* __restrict__ ext_W2,
               const float* __restrict__ ext_b2,
               float* __restrict__ out,
               int B)
{
    __shared__ SmemT sm;
    const int r = blockIdx.y;
    const int cnt = cCNT[r];
    #define ARGS &sm, r, temp, pressure, comp_h2o, comp_h2o_sq, comp_o3, comp_co2, \
                 comp_n2o, comp_ch4, comp_u, lwp, iwp, mu, mu_bar, gas_W1, gas_b1, \
                 gas_W2, gas_b2, lw_w, iw_w, ext_W1, ext_b1, ext_W2, ext_b2, out, B
    switch (cnt) {
        case 7: row_body<7>(ARGS); break;
        case 4: row_body<4>(ARGS); break;
        case 3: row_body<3>(ARGS); break;
        case 2: row_body<2>(ARGS); break;
        default: row_body<1>(ARGS); break;
    }
    #undef ARGS
}

extern "C" void kernel_launch(void* const* d_in, const int* in_sizes, int n_in,
                              void* d_out, int out_size)
{
    const int B = in_sizes[0];
    const int quads = (B + 3) / 4;
    dim3 grid((quads + TPB - 1) / TPB, 29);
    atm_row_kernel<<<grid, TPB>>>(
        (const float*)d_in[0],  (const float*)d_in[1],  (const float*)d_in[2],
        (const float*)d_in[3],  (const float*)d_in[4],  (const float*)d_in[5],
        (const float*)d_in[6],  (const float*)d_in[7],  (const float*)d_in[8],
        (const float*)d_in[9],  (const float*)d_in[10], (const float*)d_in[11],
        (const float*)d_in[12], (const float*)d_in[13], (const float*)d_in[14],
        (const float*)d_in[15], (const float*)d_in[16], (const float*)d_in[17],
        (const float*)d_in[18], (const float*)d_in[19], (const float*)d_in[20],
        (const float*)d_in[21], (const float*)d_in[22],
        (float*)d_out, B);
}

// round 15
// speedup vs baseline: 1.1289x; 1.1289x over previous
#include <cuda_runtime.h>

// AtmLayer v8: v6 (row x column-pair, f32x2 packed, select-free gas elu)
// with LDS.128-packed smem weight layout: every packed operand pair comes
// from a single 16B shared load (gas 3 LDS/unit vs 5; ext 4 LDS/j vs 8).

#define TPB 128

typedef unsigned long long u64;
union F2U { u64 u; float2 f; };

__device__ __forceinline__ float2 fma2(float2 a, float2 b, float2 c) {
    F2U A, B, C, D; A.f = a; B.f = b; C.f = c;
    asm("fma.rn.f32x2 %0,%1,%2,%3;" : "=l"(D.u) : "l"(A.u), "l"(B.u), "l"(C.u));
    return D.f;
}
__device__ __forceinline__ float2 mul2(float2 a, float2 b) {
    F2U A, B, D; A.f = a; B.f = b;
    asm("mul.rn.f32x2 %0,%1,%2;" : "=l"(D.u) : "l"(A.u), "l"(B.u));
    return D.f;
}
__device__ __forceinline__ float2 add2(float2 a, float2 b) {
    F2U A, B, D; A.f = a; B.f = b;
    asm("add.rn.f32x2 %0,%1,%2;" : "=l"(D.u) : "l"(A.u), "l"(B.u));
    return D.f;
}
__device__ __forceinline__ float ex2_(float x) {
    float r; asm("ex2.approx.ftz.f32 %0,%1;" : "=f"(r) : "f"(x)); return r;
}

#define L2E 1.4426950408889634f
#define LN2 0.6931471805599453f

// comp idx: 0=h2o 1=h2o_sq 2=o3 3=co2 4=n2o 5=ch4 6=u
__constant__ int cNETS[29][7] = {
    {23, 0,52,65,74,77,86},
    {24, 1,53,66,75,78,87},
    {25, 2,54,67,76,79,88},
    {26, 3,80,-1,-1,-1,-1},
    {27, 4,81,-1,-1,-1,-1},
    {28, 5,68,-1,-1,-1,-1},
    {29, 6,69,-1,-1,-1,-1},
    {30, 3,82,-1,-1,-1,-1},
    {31, 4,83,-1,-1,-1,-1},
    {32, 9,70,-1,-1,-1,-1},
    {33,10,71,-1,-1,-1,-1},
    {34,11,84,-1,-1,-1,-1},
    {35,12,85,-1,-1,-1,-1},
    {36,13,72,-1,-1,-1,-1},
    {37,14,73,-1,-1,-1,-1},
    {38,15,89,-1,-1,-1,-1},
    {39,16,90,-1,-1,-1,-1},
    {40,17,55,91,-1,-1,-1},
    {41,18,56,92,-1,-1,-1},
    {42,19,57,93,-1,-1,-1},
    {43,20,58,94,-1,-1,-1},
    {44,21,59,95,-1,-1,-1},
    {45,22,60,96,-1,-1,-1},
    {46,-1,-1,-1,-1,-1,-1},
    {47,-1,-1,-1,-1,-1,-1},
    {48,61,-1,-1,-1,-1,-1},
    {49,62,-1,-1,-1,-1,-1},
    {50,63,97,-1,-1,-1,-1},
    {51,64,98,-1,-1,-1,-1},
};
__constant__ int cCIDX[29][7] = {
    {1,0,2,3,4,5,6},
    {1,0,2,3,4,5,6},
    {1,0,2,3,4,5,6},
    {1,0,5,0,0,0,0},
    {1,0,5,0,0,0,0},
    {1,0,3,0,0,0,0},
    {1,0,3,0,0,0,0},
    {1,0,5,0,0,0,0},
    {1,0,5,0,0,0,0},
    {1,0,3,0,0,0,0},
    {1,0,3,0,0,0,0},
    {1,0,5,0,0,0,0},
    {1,0,5,0,0,0,0},
    {1,0,3,0,0,0,0},
    {1,0,3,0,0,0,0},
    {1,0,6,0,0,0,0},
    {1,0,6,0,0,0,0},
    {1,0,2,6,0,0,0},
    {1,0,2,6,0,0,0},
    {1,0,2,6,0,0,0},
    {1,0,2,6,0,0,0},
    {1,0,2,6,0,0,0},
    {1,0,2,6,0,0,0},
    {1,0,0,0,0,0,0},
    {1,0,0,0,0,0,0},
    {1,2,0,0,0,0,0},
    {1,2,0,0,0,0,0},
    {1,2,6,0,0,0,0},
    {1,2,6,0,0,0,0},
};
__constant__ int cCNT[29] = {7,7,7,3,3,3,3,3,3,3,3,3,3,3,3,3,3,4,4,4,4,4,4,1,1,2,2,3,3};

struct __align__(16) GasNet {
    float2 gw[8][4];   // [u]: [0]=W1_row0*L2E dup, [1]=W1_row1*L2E dup,
                       //      [2]=W2*LN2 dup,       [3]=W2 dup
    float2 gb[8];      // b1 * L2E, dup
    float  bias;       // b2 - sum(W2)
    float  pad[3];
};
struct __align__(16) SmemT {
    GasNet g[7];
    float2 ew1[16][4];   // ext W1*1 dup, [j][i]; read as 2x float4
    float2 evb[16][4];   // [j]: v0,v1,v2 dup, b1[j] dup; read as 2x float4
    float  misc[5];      // lw, iw, eb0..2
    const float* comp[7];
};

template<int CNT>
__device__ __forceinline__ void row_body(
    SmemT* sm, int r,
    const float* __restrict__ temp, const float* __restrict__ pressure,
    const float* __restrict__ comp_h2o, const float* __restrict__ comp_h2o_sq,
    const float* __restrict__ comp_o3, const float* __restrict__ comp_co2,
    const float* __restrict__ comp_n2o, const float* __restrict__ comp_ch4,
    const float* __restrict__ comp_u,
    const float* __restrict__ lwp, const float* __restrict__ iwp,
    const float* __restrict__ mu, const float* __restrict__ mu_bar,
    const float* __restrict__ gas_W1, const float* __restrict__ gas_b1,
    const float* __restrict__ gas_W2, const float* __restrict__ gas_b2,
    const float* __restrict__ lw_w, const float* __restrict__ iw_w,
    const float* __restrict__ ext_W1, const float* __restrict__ ext_b1,
    const float* __restrict__ ext_W2, const float* __restrict__ ext_b2,
    float* __restrict__ out, int B)
{
    const int tid = threadIdx.x;

    // ---- staging: transform + duplicate weights into packed layout ----
    #pragma unroll 2
    for (int i = tid; i < CNT * 33; i += TPB) {
        const int t = i / 33;
        const int k = i - t * 33;
        const int g = cNETS[r][t];
        GasNet& G = sm->g[t];
        if (k < 16) {
            const float w = gas_W1[g * 16 + k] * L2E;
            G.gw[k & 7][k >> 3] = make_float2(w, w);
        } else if (k < 24) {
            const float w = gas_b1[g * 8 + (k - 16)] * L2E;
            G.gb[k - 16] = make_float2(w, w);
        } else if (k < 32) {
            const float w = gas_W2[g * 8 + (k - 24)];
            G.gw[k - 24][2] = make_float2(w * LN2, w * LN2);
            G.gw[k - 24][3] = make_float2(w, w);
        } else {
            float s = 0.0f;
            #pragma unroll
            for (int u = 0; u < 8; ++u) s += gas_W2[g * 8 + u];
            G.bias = gas_b2[g] - s;
        }
    }
    for (int i = tid; i < 64; i += TPB) {
        const int ii = i >> 4, j = i & 15;
        const float w = ext_W1[r * 64 + i];
        sm->ew1[j][ii] = make_float2(w, w);
    }
    for (int i = tid; i < 48; i += TPB) {
        const int j = i / 3, k = i - j * 3;
        const float w = ext_W2[r * 48 + i];
        sm->evb[j][k] = make_float2(w, w);
    }
    for (int i = tid; i < 16; i += TPB) {
        const float w = ext_b1[r * 16 + i];
        sm->evb[i][3] = make_float2(w, w);
    }
    if (tid < 5) {
        float v;
        if      (tid == 0) v = lw_w[r];
        else if (tid == 1) v = iw_w[r];
        else               v = ext_b2[r * 3 + (tid - 2)];
        sm->misc[tid] = v;
    }
    if (tid >= 8 && tid < 8 + CNT) {
        const int t = tid - 8;
        const float* ptrs[7] = {comp_h2o, comp_h2o_sq, comp_o3, comp_co2,
                                comp_n2o, comp_ch4, comp_u};
        sm->comp[t] = ptrs[cCIDX[r][t]];
    }
    __syncthreads();

    const int p = blockIdx.x * TPB + tid;      // pair index
    const int b0 = 2 * p;
    if (b0 + 1 >= B) return;

    const float2 X0 = reinterpret_cast<const float2*>(temp)[p];      // (A,B)
    const float2 X1 = reinterpret_cast<const float2*>(pressure)[p];

    // ---- gas nets: packed (A,B), split-accumulator elu ----
    float2 tau = make_float2(0.0f, 0.0f);
    #pragma unroll
    for (int t = 0; t < CNT; ++t) {
        const GasNet& G = sm->g[t];
        float2 acc1 = make_float2(0.0f, 0.0f);
        float2 acc2 = make_float2(0.0f, 0.0f);
        #pragma unroll
        for (int u = 0; u < 8; ++u) {
            const float4 q0 = *reinterpret_cast<const float4*>(&G.gw[u][0]);
            const float4 q1 = *reinterpret_cast<const float4*>(&G.gw[u][2]);
            const float2 wa = make_float2(q0.x, q0.y);
            const float2 wb = make_float2(q0.z, q0.w);
            const float2 vl = make_float2(q1.x, q1.y);
            const float2 vv = make_float2(q1.z, q1.w);
            const float2 bb = G.gb[u];
            const float2 zs = fma2(X1, wb, fma2(X0, wa, bb));
            const float2 mx = make_float2(fmaxf(zs.x, 0.0f), fmaxf(zs.y, 0.0f));
            const float2 ee = make_float2(ex2_(fminf(zs.x, 0.0f)),
                                          ex2_(fminf(zs.y, 0.0f)));
            acc1 = fma2(mx, vl, acc1);
            acc2 = fma2(ee, vv, acc2);
        }
        const float2 acc = add2(acc1, acc2);
        const float keA = fmaxf(acc.x + G.bias, 0.0f);
        const float keB = fmaxf(acc.y + G.bias, 0.0f);
        const float2 cc = reinterpret_cast<const float2*>(sm->comp[t])[p];
        tau = fma2(make_float2(keA, keB), cc, tau);
    }

    // ---- cloud terms + ext inputs ----
    const float2 LWP = reinterpret_cast<const float2*>(lwp)[p];
    const float2 IWP = reinterpret_cast<const float2*>(iwp)[p];
    const float2 MUv = reinterpret_cast<const float2*>(mu)[p];
    const float2 MUB = reinterpret_cast<const float2*>(mu_bar)[p];
    const float lwr = sm->misc[0], iwr = sm->misc[1];
    const float2 tlw = mul2(make_float2(lwr, lwr), LWP);
    const float2 tiw = mul2(make_float2(iwr, iwr), IWP);
    const float2 tt  = add2(tau, add2(tlw, tiw));
    const float2 rtt = make_float2(__fdividef(1.0f, tt.x), __fdividef(1.0f, tt.y));
    const float2 I1 = mul2(tlw, rtt);
    const float2 I2 = mul2(tiw, rtt);
    const float2 I3D = make_float2(tt.x * __fdividef(1.0f, MUv.x),
                                   tt.y * __fdividef(1.0f, MUv.y));
    const float2 I3F = make_float2(tt.x * __fdividef(1.0f, MUB.x),
                                   tt.y * __fdividef(1.0f, MUB.y));

    // ---- ext net: packed (A,B), direct+diffuse share weight loads ----
    const float eb0 = sm->misc[2], eb1v = sm->misc[3], eb2v = sm->misc[4];
    float2 ad0 = make_float2(eb0, eb0), ad1 = make_float2(eb1v, eb1v), ad2 = make_float2(eb2v, eb2v);
    float2 af0 = ad0, af1 = ad1, af2 = ad2;
    const float2 L2E2 = make_float2(L2E, L2E);
    #pragma unroll
    for (int j = 0; j < 16; ++j) {
        const float4 e0 = *reinterpret_cast<const float4*>(&sm->ew1[j][0]);
        const float4 e1 = *reinterpret_cast<const float4*>(&sm->ew1[j][2]);
        const float4 e2 = *reinterpret_cast<const float4*>(&sm->evb[j][0]);
        const float4 e3 = *reinterpret_cast<const float4*>(&sm->evb[j][2]);
        const float2 w0  = make_float2(e0.x, e0.y);
        const float2 w1v = make_float2(e0.z, e0.w);
        const float2 w2v = make_float2(e1.x, e1.y);
        const float2 w3v = make_float2(e1.z, e1.w);
        const float2 v0  = make_float2(e2.x, e2.y);
        const float2 v1  = make_float2(e2.z, e2.w);
        const float2 v2  = make_float2(e3.x, e3.y);
        const float2 bj  = make_float2(e3.z, e3.w);
        const float2 base = fma2(I2, w1v, fma2(I1, w0, bj));
        const float2 zd = fma2(MUv, w3v, fma2(I3D, w2v, base));
        const float2 zf = fma2(MUB, w3v, fma2(I3F, w2v, base));
        const float2 td = mul2(zd, L2E2);
        const float2 tf = mul2(zf, L2E2);
        float2 hd, hf;
        hd.x = zd.x > 0.0f ? zd.x : ex2_(td.x) - 1.0f;
        hd.y = zd.y > 0.0f ? zd.y : ex2_(td.y) - 1.0f;
        hf.x = zf.x > 0.0f ? zf.x : ex2_(tf.x) - 1.0f;
        hf.y = zf.y > 0.0f ? zf.y : ex2_(tf.y) - 1.0f;
        ad0 = fma2(hd, v0, ad0); ad1 = fma2(hd, v1, ad1); ad2 = fma2(hd, v2, ad2);
        af0 = fma2(hf, v0, af0); af1 = fma2(hf, v1, af1); af2 = fma2(hf, v2, af2);
    }

    const unsigned NB = (unsigned)B * 29u;
    const unsigned rb = (unsigned)r * (unsigned)B + (unsigned)b0;
    const unsigned ebase = rb * 3u;

    // softmax (direct, cols A+B) -> 3 float2 stores
    {
        const float a0 = fmaxf(ad0.x, 0.0f), a1 = fmaxf(ad1.x, 0.0f), a2 = fmaxf(ad2.x, 0.0f);
        const float m = fmaxf(a0, fmaxf(a1, a2));
        const float e0 = ex2_((a0 - m) * L2E), e1 = ex2_((a1 - m) * L2E), e2 = ex2_((a2 - m) * L2E);
        const float inv = __fdividef(1.0f, e0 + e1 + e2);
        const float b0v = fmaxf(ad0.y, 0.0f), b1v = fmaxf(ad1.y, 0.0f), b2v = fmaxf(ad2.y, 0.0f);
        const float mB = fmaxf(b0v, fmaxf(b1v, b2v));
        const float f0 = ex2_((b0v - mB) * L2E), f1 = ex2_((b1v - mB) * L2E), f2 = ex2_((b2v - mB) * L2E);
        const float invB = __fdividef(1.0f, f0 + f1 + f2);
        float2* o = reinterpret_cast<float2*>(out + 2u * NB + ebase);
        o[0] = make_float2(e0 * inv, e1 * inv);
        o[1] = make_float2(e2 * inv, f0 * invB);
        o[2] = make_float2(f1 * invB, f2 * invB);
    }
    // softmax (diffuse)
    {
        const float a0 = fmaxf(af0.x, 0.0f), a1 = fmaxf(af1.x, 0.0f), a2 = fmaxf(af2.x, 0.0f);
        const float m = fmaxf(a0, fmaxf(a1, a2));
        const float e0 = ex2_((a0 - m) * L2E), e1 = ex2_((a1 - m) * L2E), e2 = ex2_((a2 - m) * L2E);
        const float inv = __fdividef(1.0f, e0 + e1 + e2);
        const float b0v = fmaxf(af0.y, 0.0f), b1v = fmaxf(af1.y, 0.0f), b2v = fmaxf(af2.y, 0.0f);
        const float mB = fmaxf(b0v, fmaxf(b1v, b2v));
        const float f0 = ex2_((b0v - mB) * L2E), f1 = ex2_((b1v - mB) * L2E), f2 = ex2_((b2v - mB) * L2E);
        const float invB = __fdividef(1.0f, f0 + f1 + f2);
        float2* o = reinterpret_cast<float2*>(out + 5u * NB + ebase);
        o[0] = make_float2(e0 * inv, e1 * inv);
        o[1] = make_float2(e2 * inv, f0 * invB);
        o[2] = make_float2(f1 * invB, f2 * invB);
    }
    {
        const float2 nd = mul2(I3D, make_float2(-L2E, -L2E));
        const float2 nf = mul2(I3F, make_float2(-L2E, -L2E));
        reinterpret_cast<float2*>(out + rb)[0]      = make_float2(ex2_(nd.x), ex2_(nd.y));
        reinterpret_cast<float2*>(out + NB + rb)[0] = make_float2(ex2_(nf.x), ex2_(nf.y));
    }
}

__global__ void __launch_bounds__(TPB)
atm_row_kernel(const float* __restrict__ temp,
               const float* __restrict__ pressure,
               const float* __restrict__ comp_h2o,
               const float* __restrict__ comp_h2o_sq,
               const float* __restrict__ comp_o3,
               const float* __restrict__ comp_co2,
               const float* __restrict__ comp_n2o,
               const float* __restrict__ comp_ch4,
               const float* __restrict__ comp_u,
               const float* __restrict__ lwp,
               const float* __restrict__ iwp,
               const float* __restrict__ mu,
               const float* __restrict__ mu_bar,
               const float* __restrict__ gas_W1,
               const float* __restrict__ gas_b1,
               const float* __restrict__ gas_W2,
               const float* __restrict__ gas_b2,
               const float* __restrict__ lw_w,
               const float* __restrict__ iw_w,
               const float* __restrict__ ext_W1,
               const float* __restrict__ ext_b1,
               const float* __restrict__ ext_W2,
               const float* __restrict__ ext_b2,
               float* __restrict__ out,
               int B)
{
    __shared__ SmemT sm;
    const int r = blockIdx.y;
    const int cnt = cCNT[r];
    #define ARGS &sm, r, temp, pressure, comp_h2o, comp_h2o_sq, comp_o3, comp_co2, \
                 comp_n2o, comp_ch4, comp_u, lwp, iwp, mu, mu_bar, gas_W1, gas_b1, \
                 gas_W2, gas_b2, lw_w, iw_w, ext_W1, ext_b1, ext_W2, ext_b2, out, B
    switch (cnt) {
        case 7: row_body<7>(ARGS); break;
        case 4: row_body<4>(ARGS); break;
        case 3: row_body<3>(ARGS); break;
        case 2: row_body<2>(ARGS); break;
        default: row_body<1>(ARGS); break;
    }
    #undef ARGS
}

extern "C" void kernel_launch(void* const* d_in, const int* in_sizes, int n_in,
                              void* d_out, int out_size)
{
    const int B = in_sizes[0];
    const int pairs = (B + 1) / 2;
    dim3 grid((pairs + TPB - 1) / TPB, 29);
    atm_row_kernel<<<grid, TPB>>>(
        (const float*)d_in[0],  (const float*)d_in[1],  (const float*)d_in[2],
        (const float*)d_in[3],  (const float*)d_in[4],  (const float*)d_in[5],
        (const float*)d_in[6],  (const float*)d_in[7],  (const float*)d_in[8],
        (const float*)d_in[9],  (const float*)d_in[10], (const float*)d_in[11],
        (const float*)d_in[12], (const float*)d_in[13], (const float*)d_in[14],
        (const float*)d_in[15], (const float*)d_in[16], (const float*)d_in[17],
        (const float*)d_in[18], (const float*)d_in[19], (const float*)d_in[20],
        (const float*)d_in[21], (const float*)d_in[22],
        (float*)d_out, B);
}